// round 14
// baseline (speedup 1.0000x reference)
#include <cuda_runtime.h>
#include <cuda_fp16.h>
#include <stdint.h>
#include <string.h>

// ---------------- problem constants ----------------
#define B_   2
#define N_   512
#define D_   64
#define H_   128
#define OUT_ 64
#define CPG  18                  // i-stride: CTAs per (b, j-block) group
#define GRID_MAIN (B_ * 4 * CPG) // 144 CTAs, ~1 per SM

// ---------------- device scratch (no allocs allowed) ----------------
__device__ __align__(16) __half g_xa [B_ * N_ * H_];   // x @ W1[:D]       (fp16)
__device__ __align__(16) __half g_xbp[B_ * N_ * H_];   // x @ W1[D:] + b1  (fp16)
__device__ float g_part[GRID_MAIN * H_];               // per-CTA pooled partials

__device__ __forceinline__ __half2 as_h2(uint32_t u) { __half2 h; memcpy(&h, &u, 4); return h; }
__device__ __forceinline__ uint32_t as_u32(__half2 h) { uint32_t u; memcpy(&u, &h, 4); return u; }

// relu(a + b) on packed half2
__device__ __forceinline__ uint32_t relu_add2(uint32_t a, uint32_t b) {
    __half2 z = __float2half2_rn(0.f);
    return as_u32(__hmax2(__hadd2(as_h2(a), as_h2(b)), z));
}

// m16n8k16 row.col fp16 x fp16 -> fp16 accumulate (baseline PTX, sm_80+)
__device__ __forceinline__ void mma16816h(uint32_t* c, const uint32_t* a, uint32_t b0, uint32_t b1) {
    asm volatile(
        "mma.sync.aligned.m16n8k16.row.col.f16.f16.f16.f16 "
        "{%0,%1}, {%2,%3,%4,%5}, {%6,%7}, {%0,%1};"
        : "+r"(c[0]), "+r"(c[1])
        : "r"(a[0]), "r"(a[1]), "r"(a[2]), "r"(a[3]), "r"(b0), "r"(b1));
}

// ---------------- main-kernel SMEM layout (dynamic) ----------------
// W2F : 0      32768  (W2 fragments, [k8][nt16][lane32] x 8B)
// XA  : 32768  34816  (128 rows x 272B padded fp16; staged once, read to regs)
// RED : 67584  4096   (16 warps x 64 cols fp32)
// B2  : 71680  512
#define SOFF_W2F 0
#define SOFF_XA  32768
#define SOFF_RED 67584
#define SOFF_B2  71680
#define XA_STRIDE 272
#define SMEM_MAIN (71680 + 512)

// prep smem: W1 staged (128x128 f32 = 64KB) + x rows (8x64 f32 = 2KB)
#define SMEM_PREP (128 * 128 * 4 + 8 * 64 * 4)

// =====================================================================
// Kernel 1: prep — xa = x @ W1[:64] (fp16), xbp = x @ W1[64:] + b1 (fp16)
// 128 blocks (single wave) x 256 threads, W1 staged in smem (no LDG chains,
// no 64-reg weight array). threads 0-127 -> xa, 128-255 -> xbp; 8 rows/block.
// =====================================================================
__global__ void __launch_bounds__(256) prep_kernel(const float* __restrict__ x,
                                                   const float* __restrict__ W1,
                                                   const float* __restrict__ b1) {
    extern __shared__ float sm[];
    float* W1s = sm;                 // [d=128][h=128]
    float* xs  = sm + 128 * 128;     // [rr=8][d=64]

    int tid  = threadIdx.x;
    int row0 = blockIdx.x * 8;

    for (int q = tid; q < 128 * 128; q += 256) W1s[q] = W1[q];
    for (int q = tid; q < 8 * 64;   q += 256) xs[q]  = x[row0 * 64 + q];
    __syncthreads();

    int h    = tid & 127;
    int half = tid >> 7;             // 0 -> xa, 1 -> xbp
    float bb = half ? b1[h] : 0.f;
    const float* Wcol = W1s + half * 64 * 128 + h;

    #pragma unroll 1
    for (int rr = 0; rr < 8; rr++) {
        const float* xr = xs + rr * 64;
        float p0 = 0.f, p1 = 0.f, p2 = 0.f, p3 = 0.f;
        #pragma unroll
        for (int d = 0; d < 64; d += 4) {
            p0 += xr[d]     * Wcol[d * 128];
            p1 += xr[d + 1] * Wcol[(d + 1) * 128];
            p2 += xr[d + 2] * Wcol[(d + 2) * 128];
            p3 += xr[d + 3] * Wcol[(d + 3) * 128];
        }
        float s = bb + ((p0 + p1) + (p2 + p3));
        int row = row0 + rr;
        if (half) g_xbp[row * H_ + h] = __float2half(s);
        else      g_xa [row * H_ + h] = __float2half(s);
    }
}

// =====================================================================
// Kernel 2: main — 512 threads (4 warps/SMSP) to hide HMMA/LDS latency.
// Each warp: 16 rows (wm=wid&7) x 64 cols (wn=wid>>3). xa fragments in
// registers (invariant across tiles); fp16 accumulators; pooled in fp32.
// =====================================================================
__global__ void __launch_bounds__(512, 1) main_kernel(const float* __restrict__ W2,
                                                      const float* __restrict__ b2) {
    extern __shared__ char smem[];

    int tid  = threadIdx.x;
    int wid  = tid >> 5;
    int lane = tid & 31;
    int tig  = lane & 3;      // k-pair / n-parity selector
    int g    = lane >> 2;     // row within 8
    int wn   = wid >> 3;      // warp col half: 0 -> cols 0..63, 1 -> 64..127
    int wm   = wid & 7;       // warp row 16-group: rows wm*16 .. wm*16+15

    int grp = blockIdx.x / CPG;   // 0..7 : (b, jb)
    int cig = blockIdx.x % CPG;
    int b   = grp >> 2;
    int jb  = grp & 3;
    int ntiles = (N_ - cig + CPG - 1) / CPG;   // 28 or 29

    // --- pack W2 into fragment-ordered smem: entry (k, nt, lane) -> 8 bytes ---
    for (int idx = tid; idx < 8 * 16 * 32; idx += 512) {
        int li = idx & 31, nt = (idx >> 5) & 15, k = idx >> 9;
        int ltig = li & 3, lg = li >> 2;
        int col = nt * 8 + lg;
        int r0 = k * 16 + ltig * 2;
        uint32_t v0 = as_u32(__floats2half2_rn(W2[r0 * H_ + col],       W2[(r0 + 1) * H_ + col]));
        uint32_t v1 = as_u32(__floats2half2_rn(W2[(r0 + 8) * H_ + col], W2[(r0 + 9) * H_ + col]));
        *(uint2*)(smem + SOFF_W2F + idx * 8) = make_uint2(v0, v1);
    }

    // --- stage xa tile (b, jb): 128 rows x 128 fp16, 272B padded stride ---
    {
        const float4* xag = (const float4*)(g_xa + (size_t)(b * N_ + jb * 128) * H_);
        for (int q = tid; q < 128 * 16; q += 512) {
            int r = q >> 4, f = q & 15;
            *(float4*)(smem + SOFF_XA + r * XA_STRIDE + f * 16) = xag[q];
        }
    }

    // --- b2 to smem (fp32) ---
    if (tid < 128) *(float*)(smem + SOFF_B2 + tid * 4) = b2[tid];

    __syncthreads();

    // --- hoist this thread's xa fragments into registers (invariant) ---
    // rows: wm*16 + g (+8); cols: k*16 + tig*2 (+8)
    uint32_t xar[8][4];
    {
        const char* xa_base = smem + SOFF_XA + (wm * 16 + g) * XA_STRIDE + tig * 4;
        #pragma unroll
        for (int k = 0; k < 8; k++) {
            const char* p0 = xa_base + k * 32;
            const char* p1 = p0 + 8 * XA_STRIDE;
            xar[k][0] = *(const uint32_t*)(p0);
            xar[k][1] = *(const uint32_t*)(p1);
            xar[k][2] = *(const uint32_t*)(p0 + 16);
            xar[k][3] = *(const uint32_t*)(p1 + 16);
        }
    }

    // --- per-thread b2 half2 biases for the epilogue ---
    uint32_t b2h[8];
    {
        const float* b2s = (const float*)(smem + SOFF_B2);
        #pragma unroll
        for (int n = 0; n < 8; n++) {
            int col = wn * 64 + n * 8 + tig * 2;
            b2h[n] = as_u32(__floats2half2_rn(b2s[col], b2s[col + 1]));
        }
    }

    const char* w2f_base = smem + SOFF_W2F + (size_t)(wn * 8) * 32 * 8 + lane * 8;
    const uint32_t* xbp_rows = (const uint32_t*)(g_xbp + (size_t)(b * N_) * H_);

    float pooled[8][2];
    #pragma unroll
    for (int n = 0; n < 8; n++) { pooled[n][0] = 0.f; pooled[n][1] = 0.f; }

    auto load_xb = [&](uint32_t* xb, int i) {
        const uint32_t* row = xbp_rows + (size_t)i * (H_ / 2);
        #pragma unroll
        for (int k = 0; k < 8; k++) {
            xb[k * 2]     = __ldg(row + k * 8 + tig);
            xb[k * 2 + 1] = __ldg(row + k * 8 + tig + 4);
        }
    };

    auto compute_tile = [&](const uint32_t* xb) {
        uint32_t acc[8][2];
        #pragma unroll
        for (int n = 0; n < 8; n++) { acc[n][0] = 0u; acc[n][1] = 0u; }

        #pragma unroll
        for (int k = 0; k < 8; k++) {
            uint32_t xb0 = xb[k * 2], xb1 = xb[k * 2 + 1];
            uint32_t a[4];
            a[0] = relu_add2(xar[k][0], xb0);
            a[1] = relu_add2(xar[k][1], xb0);
            a[2] = relu_add2(xar[k][2], xb1);
            a[3] = relu_add2(xar[k][3], xb1);
            const char* wp = w2f_base + (size_t)k * 16 * 32 * 8;
            #pragma unroll
            for (int n = 0; n < 8; n++) {
                uint2 bf = *(const uint2*)(wp + (size_t)n * 32 * 8);
                mma16816h(acc[n], a, bf.x, bf.y);
            }
        }

        // epilogue: pooled[col] += relu(acc + b2) over the 2 row-fragments (fp32)
        __half2 z = __float2half2_rn(0.f);
        #pragma unroll
        for (int n = 0; n < 8; n++) {
            __half2 r0 = __hmax2(__hadd2(as_h2(acc[n][0]), as_h2(b2h[n])), z);
            __half2 r1 = __hmax2(__hadd2(as_h2(acc[n][1]), as_h2(b2h[n])), z);
            float2 f0 = __half22float2(r0);
            float2 f1 = __half22float2(r1);
            pooled[n][0] += f0.x + f1.x;
            pooled[n][1] += f0.y + f1.y;
        }
    };

    // --- software-pipelined tile loop (xb prefetch in regs, no barriers) ---
    uint32_t xbA[16], xbB[16];
    load_xb(xbA, cig);
    for (int t = 0; t < ntiles; t += 2) {
        if (t + 1 < ntiles) load_xb(xbB, cig + (t + 1) * CPG);
        compute_tile(xbA);
        if (t + 1 < ntiles) {
            if (t + 2 < ntiles) load_xb(xbA, cig + (t + 2) * CPG);
            compute_tile(xbB);
        }
    }

    // --- deterministic reduction: shfl over rows, smem over warps ---
    float* red = (float*)(smem + SOFF_RED);
    #pragma unroll
    for (int n = 0; n < 8; n++) {
        #pragma unroll
        for (int p = 0; p < 2; p++) {
            float v = pooled[n][p];
            v += __shfl_xor_sync(0xFFFFFFFFu, v, 4);
            v += __shfl_xor_sync(0xFFFFFFFFu, v, 8);
            v += __shfl_xor_sync(0xFFFFFFFFu, v, 16);
            if (lane < 4) red[wid * 64 + n * 8 + lane * 2 + p] = v;
        }
    }
    __syncthreads();

    if (tid < 128) {
        int col = tid;
        int wbase = (col >> 6) * 8;          // 8 warps share this column half
        int cl = col & 63;
        float s = 0.f;
        #pragma unroll
        for (int w = 0; w < 8; w++) s += red[(wbase + w) * 64 + cl];
        g_part[blockIdx.x * H_ + col] = s;
    }
}

// =====================================================================
// Kernel 3: finish — pooled = S@W3 + N^2*b3 ; o = relu(pooled@V1+c1) ; out = o@V2+c2
// =====================================================================
__global__ void __launch_bounds__(128) finish_kernel(const float* __restrict__ W3,
                                                     const float* __restrict__ b3,
                                                     const float* __restrict__ V1,
                                                     const float* __restrict__ c1,
                                                     const float* __restrict__ V2,
                                                     const float* __restrict__ c2,
                                                     float* __restrict__ out) {
    int b = blockIdx.x, h = threadIdx.x;
    __shared__ float S[128], P[128], O[128];

    float s = 0.f;
    #pragma unroll 8
    for (int c = 0; c < 4 * CPG; c++)
        s += g_part[(b * 4 * CPG + c) * H_ + h];
    S[h] = s;
    __syncthreads();

    float p = (float)(N_) * (float)(N_) * b3[h];
    #pragma unroll 8
    for (int kk = 0; kk < 128; kk++) p += S[kk] * W3[kk * H_ + h];
    P[h] = p;
    __syncthreads();

    float o = c1[h];
    #pragma unroll 8
    for (int kk = 0; kk < 128; kk++) o += P[kk] * V1[kk * H_ + h];
    O[h] = fmaxf(o, 0.f);
    __syncthreads();

    if (h < OUT_) {
        float r = c2[h];
        #pragma unroll 8
        for (int kk = 0; kk < 128; kk++) r += O[kk] * V2[kk * OUT_ + h];
        out[b * OUT_ + h] = r;
    }
}

// =====================================================================
extern "C" void kernel_launch(void* const* d_in, const int* in_sizes, int n_in,
                              void* d_out, int out_size) {
    (void)in_sizes; (void)n_in; (void)out_size;
    const float* x  = (const float*)d_in[0];
    const float* W1 = (const float*)d_in[1];
    const float* b1 = (const float*)d_in[2];
    const float* W2 = (const float*)d_in[3];
    const float* b2 = (const float*)d_in[4];
    const float* W3 = (const float*)d_in[5];
    const float* b3 = (const float*)d_in[6];
    const float* V1 = (const float*)d_in[7];
    const float* c1 = (const float*)d_in[8];
    const float* V2 = (const float*)d_in[9];
    const float* c2 = (const float*)d_in[10];
    float* out = (float*)d_out;

    cudaFuncSetAttribute(prep_kernel, cudaFuncAttributeMaxDynamicSharedMemorySize, SMEM_PREP);
    cudaFuncSetAttribute(main_kernel, cudaFuncAttributeMaxDynamicSharedMemorySize, SMEM_MAIN);

    prep_kernel<<<(B_ * N_) / 8, 256, SMEM_PREP>>>(x, W1, b1);
    main_kernel<<<GRID_MAIN, 512, SMEM_MAIN>>>(W2, b2);
    finish_kernel<<<B_, 128>>>(W3, b3, V1, c1, V2, c2, out);
}

// round 15
// speedup vs baseline: 1.6975x; 1.6975x over previous
#include <cuda_runtime.h>
#include <cuda_fp16.h>
#include <stdint.h>
#include <string.h>

// ---------------- problem constants ----------------
#define B_   2
#define N_   512
#define D_   64
#define H_   128
#define OUT_ 64
#define CPG  18                  // i-stride: CTAs per (b, j-block) group
#define GRID_MAIN (B_ * 4 * CPG) // 144 CTAs, ~1 per SM

// ---------------- device scratch (no allocs allowed) ----------------
__device__ __align__(16) __half g_xa [B_ * N_ * H_];   // x @ W1[:D]       (fp16)
__device__ __align__(16) __half g_xbp[B_ * N_ * H_];   // x @ W1[D:] + b1  (fp16)
__device__ __align__(16) __half g_w1t[H_ * H_];        // W1 transposed fp16: [h][d]
__device__ __align__(16) uint2  g_w2f[8 * 16 * 32];    // W2 fragment-packed fp16
__device__ float g_part[GRID_MAIN * H_];               // per-CTA pooled partials

__device__ __forceinline__ __half2 as_h2(uint32_t u) { __half2 h; memcpy(&h, &u, 4); return h; }
__device__ __forceinline__ uint32_t as_u32(__half2 h) { uint32_t u; memcpy(&u, &h, 4); return u; }

// relu(a + b) on packed half2
__device__ __forceinline__ uint32_t relu_add2(uint32_t a, uint32_t b) {
    __half2 z = __float2half2_rn(0.f);
    return as_u32(__hmax2(__hadd2(as_h2(a), as_h2(b)), z));
}

// m16n8k16 row.col fp16 x fp16 -> fp16 accumulate (baseline PTX, sm_80+)
__device__ __forceinline__ void mma16816h(uint32_t* c, const uint32_t* a, uint32_t b0, uint32_t b1) {
    asm volatile(
        "mma.sync.aligned.m16n8k16.row.col.f16.f16.f16.f16 "
        "{%0,%1}, {%2,%3,%4,%5}, {%6,%7}, {%0,%1};"
        : "+r"(c[0]), "+r"(c[1])
        : "r"(a[0]), "r"(a[1]), "r"(a[2]), "r"(a[3]), "r"(b0), "r"(b1));
}

// ---------------- main-kernel SMEM layout (dynamic) ----------------
// W2F : 0      32768  (W2 fragments, [k8][nt16][lane32] x 8B; copied from g_w2f)
// XA  : 32768  34816  (128 rows x 272B padded fp16; staged once, read to regs)
// RED : 67584  2048   (8 warps x 64 cols fp32)
// B2  : 69632  512
#define SOFF_W2F 0
#define SOFF_XA  32768
#define SOFF_RED 67584
#define SOFF_B2  69632
#define XA_STRIDE 272
#define SMEM_MAIN (69632 + 512)

// =====================================================================
// Kernel 0: convert — W1 -> g_w1t (fp16, transposed), W2 -> g_w2f (packed frags)
// =====================================================================
__global__ void __launch_bounds__(256) convert_kernel(const float* __restrict__ W1,
                                                      const float* __restrict__ W2) {
    int i = blockIdx.x * 256 + threadIdx.x;
    if (i < H_ * H_) {
        int d = i >> 7, h = i & 127;
        g_w1t[h * H_ + d] = __float2half(W1[i]);   // coalesced read, scattered 2B write (tiny)
    }
    if (i < 8 * 16 * 32) {
        int li = i & 31, nt = (i >> 5) & 15, k = i >> 9;
        int ltig = li & 3, lg = li >> 2;
        int col = nt * 8 + lg;
        int r0 = k * 16 + ltig * 2;
        uint32_t v0 = as_u32(__floats2half2_rn(W2[r0 * H_ + col],       W2[(r0 + 1) * H_ + col]));
        uint32_t v1 = as_u32(__floats2half2_rn(W2[(r0 + 8) * H_ + col], W2[(r0 + 9) * H_ + col]));
        g_w2f[i] = make_uint2(v0, v1);
    }
}

// =====================================================================
// Kernel 1: prep — xa = x @ W1[:64] (fp16), xbp = x @ W1[64:] + b1 (fp16)
// 512 blocks x 256 threads, 2 rows/block (grid large enough to fill SMs).
// Weights: 64 fp16 from g_w1t via 8 x uint4 LDG (32 regs). fp32 accumulation.
// =====================================================================
__global__ void __launch_bounds__(256) prep_kernel(const float* __restrict__ x,
                                                   const float* __restrict__ b1) {
    __shared__ float xs[2][64];
    int tid  = threadIdx.x;
    int h    = tid & 127;
    int half = tid >> 7;                  // 0 -> xa, 1 -> xbp
    int row0 = blockIdx.x * 2;

    for (int q = tid; q < 2 * 64; q += 256)
        xs[q >> 6][q & 63] = x[row0 * 64 + q];

    // 64 fp16 weights for column h, d-range [half*64, half*64+64)
    uint32_t w[32];
    {
        const uint4* wp = (const uint4*)(g_w1t + h * H_ + half * 64);
        #pragma unroll
        for (int q = 0; q < 8; q++) {
            uint4 v = wp[q];
            w[q * 4]     = v.x;
            w[q * 4 + 1] = v.y;
            w[q * 4 + 2] = v.z;
            w[q * 4 + 3] = v.w;
        }
    }
    float bb = half ? b1[h] : 0.f;
    __syncthreads();

    #pragma unroll
    for (int rr = 0; rr < 2; rr++) {
        const float* xr = xs[rr];
        float p0 = 0.f, p1 = 0.f, p2 = 0.f, p3 = 0.f;
        #pragma unroll
        for (int q = 0; q < 32; q += 2) {
            float2 f0 = __half22float2(as_h2(w[q]));
            float2 f1 = __half22float2(as_h2(w[q + 1]));
            p0 += xr[2 * q]     * f0.x;
            p1 += xr[2 * q + 1] * f0.y;
            p2 += xr[2 * q + 2] * f1.x;
            p3 += xr[2 * q + 3] * f1.y;
        }
        float s = bb + ((p0 + p1) + (p2 + p3));
        int row = row0 + rr;
        if (half) g_xbp[row * H_ + h] = __float2half(s);
        else      g_xa [row * H_ + h] = __float2half(s);
    }
}

// =====================================================================
// Kernel 2: main — 256 threads, 8 warps (R10 proven config).
// Each warp: 32 rows x 64 cols. xa fragments in registers (invariant
// across tiles); fp16 accumulators; pooled in fp32; no barriers in loop.
// =====================================================================
__global__ void __launch_bounds__(256, 1) main_kernel(const float* __restrict__ b2) {
    extern __shared__ char smem[];

    int tid  = threadIdx.x;
    int wid  = tid >> 5;
    int lane = tid & 31;
    int tig  = lane & 3;      // k-pair / n-parity selector
    int g    = lane >> 2;     // row within 8
    int wn   = wid >> 2;      // warp col half: 0 -> cols 0..63, 1 -> 64..127
    int wm   = wid & 3;       // warp row quarter

    int grp = blockIdx.x / CPG;   // 0..7 : (b, jb)
    int cig = blockIdx.x % CPG;
    int b   = grp >> 2;
    int jb  = grp & 3;
    int ntiles = (N_ - cig + CPG - 1) / CPG;   // 28 or 29

    // --- copy pre-packed W2 fragments into smem ---
    {
        uint2* dst = (uint2*)(smem + SOFF_W2F);
        for (int idx = tid; idx < 8 * 16 * 32; idx += 256)
            dst[idx] = g_w2f[idx];
    }

    // --- stage xa tile (b, jb): 128 rows x 128 fp16, 272B padded stride ---
    {
        const float4* xag = (const float4*)(g_xa + (size_t)(b * N_ + jb * 128) * H_);
        for (int q = tid; q < 128 * 16; q += 256) {
            int r = q >> 4, f = q & 15;
            *(float4*)(smem + SOFF_XA + r * XA_STRIDE + f * 16) = xag[q];
        }
    }

    // --- b2 to smem (fp32) ---
    if (tid < 128) *(float*)(smem + SOFF_B2 + tid * 4) = b2[tid];

    __syncthreads();

    // --- hoist this thread's xa fragments into registers (invariant) ---
    uint32_t xar[8][8];   // [k][mt*4 + frag]
    {
        const char* xa_base = smem + SOFF_XA + (wm * 32 + g) * XA_STRIDE + tig * 4;
        #pragma unroll
        for (int k = 0; k < 8; k++) {
            #pragma unroll
            for (int mt = 0; mt < 2; mt++) {
                const char* p0 = xa_base + mt * 16 * XA_STRIDE + k * 32;
                const char* p1 = p0 + 8 * XA_STRIDE;
                xar[k][mt * 4 + 0] = *(const uint32_t*)(p0);
                xar[k][mt * 4 + 1] = *(const uint32_t*)(p1);
                xar[k][mt * 4 + 2] = *(const uint32_t*)(p0 + 16);
                xar[k][mt * 4 + 3] = *(const uint32_t*)(p1 + 16);
            }
        }
    }

    // --- per-thread b2 half2 biases for the epilogue ---
    uint32_t b2h[8];
    {
        const float* b2s = (const float*)(smem + SOFF_B2);
        #pragma unroll
        for (int n = 0; n < 8; n++) {
            int col = wn * 64 + n * 8 + tig * 2;
            b2h[n] = as_u32(__floats2half2_rn(b2s[col], b2s[col + 1]));
        }
    }

    const char* w2f_base = smem + SOFF_W2F + (size_t)(wn * 8) * 32 * 8 + lane * 8;
    const uint32_t* xbp_rows = (const uint32_t*)(g_xbp + (size_t)(b * N_) * H_);

    float pooled[8][2];
    #pragma unroll
    for (int n = 0; n < 8; n++) { pooled[n][0] = 0.f; pooled[n][1] = 0.f; }

    auto load_xb = [&](uint32_t* xb, int i) {
        const uint32_t* row = xbp_rows + (size_t)i * (H_ / 2);
        #pragma unroll
        for (int k = 0; k < 8; k++) {
            xb[k * 2]     = __ldg(row + k * 8 + tig);
            xb[k * 2 + 1] = __ldg(row + k * 8 + tig + 4);
        }
    };

    auto compute_tile = [&](const uint32_t* xb) {
        uint32_t acc[2][8][2];
        #pragma unroll
        for (int mt = 0; mt < 2; mt++)
            #pragma unroll
            for (int n = 0; n < 8; n++) { acc[mt][n][0] = 0u; acc[mt][n][1] = 0u; }

        #pragma unroll
        for (int k = 0; k < 8; k++) {
            uint32_t xb0 = xb[k * 2], xb1 = xb[k * 2 + 1];
            uint32_t a[2][4];
            #pragma unroll
            for (int mt = 0; mt < 2; mt++) {
                a[mt][0] = relu_add2(xar[k][mt * 4 + 0], xb0);
                a[mt][1] = relu_add2(xar[k][mt * 4 + 1], xb0);
                a[mt][2] = relu_add2(xar[k][mt * 4 + 2], xb1);
                a[mt][3] = relu_add2(xar[k][mt * 4 + 3], xb1);
            }
            const char* wp = w2f_base + (size_t)k * 16 * 32 * 8;
            #pragma unroll
            for (int n = 0; n < 8; n++) {
                uint2 bf = *(const uint2*)(wp + (size_t)n * 32 * 8);
                mma16816h(acc[0][n], a[0], bf.x, bf.y);
                mma16816h(acc[1][n], a[1], bf.x, bf.y);
            }
        }

        // epilogue: pooled[col] += relu(acc + b2) over the 4 row-fragments (fp32)
        __half2 z = __float2half2_rn(0.f);
        #pragma unroll
        for (int n = 0; n < 8; n++) {
            #pragma unroll
            for (int mt = 0; mt < 2; mt++) {
                __half2 r0 = __hmax2(__hadd2(as_h2(acc[mt][n][0]), as_h2(b2h[n])), z);
                __half2 r1 = __hmax2(__hadd2(as_h2(acc[mt][n][1]), as_h2(b2h[n])), z);
                float2 f0 = __half22float2(r0);
                float2 f1 = __half22float2(r1);
                pooled[n][0] += f0.x + f1.x;
                pooled[n][1] += f0.y + f1.y;
            }
        }
    };

    // --- software-pipelined tile loop (xb prefetch in regs, no barriers) ---
    uint32_t xbA[16], xbB[16];
    load_xb(xbA, cig);
    for (int t = 0; t < ntiles; t += 2) {
        if (t + 1 < ntiles) load_xb(xbB, cig + (t + 1) * CPG);
        compute_tile(xbA);
        if (t + 1 < ntiles) {
            if (t + 2 < ntiles) load_xb(xbA, cig + (t + 2) * CPG);
            compute_tile(xbB);
        }
    }

    // --- deterministic reduction: shfl over rows, smem over warps ---
    float* red = (float*)(smem + SOFF_RED);
    #pragma unroll
    for (int n = 0; n < 8; n++) {
        #pragma unroll
        for (int p = 0; p < 2; p++) {
            float v = pooled[n][p];
            v += __shfl_xor_sync(0xFFFFFFFFu, v, 4);
            v += __shfl_xor_sync(0xFFFFFFFFu, v, 8);
            v += __shfl_xor_sync(0xFFFFFFFFu, v, 16);
            if (lane < 4) red[wid * 64 + n * 8 + lane * 2 + p] = v;
        }
    }
    __syncthreads();

    if (tid < 128) {
        int col = tid;
        int wbase = (col >> 6) * 4;
        int cl = col & 63;
        float s = red[(wbase + 0) * 64 + cl] + red[(wbase + 1) * 64 + cl]
                + red[(wbase + 2) * 64 + cl] + red[(wbase + 3) * 64 + cl];
        g_part[blockIdx.x * H_ + col] = s;
    }
}

// =====================================================================
// Kernel 3: finish — pooled = S@W3 + N^2*b3 ; o = relu(pooled@V1+c1) ; out = o@V2+c2
// =====================================================================
__global__ void __launch_bounds__(128) finish_kernel(const float* __restrict__ W3,
                                                     const float* __restrict__ b3,
                                                     const float* __restrict__ V1,
                                                     const float* __restrict__ c1,
                                                     const float* __restrict__ V2,
                                                     const float* __restrict__ c2,
                                                     float* __restrict__ out) {
    int b = blockIdx.x, h = threadIdx.x;
    __shared__ float S[128], P[128], O[128];

    float s = 0.f;
    #pragma unroll 8
    for (int c = 0; c < 4 * CPG; c++)
        s += g_part[(b * 4 * CPG + c) * H_ + h];
    S[h] = s;
    __syncthreads();

    float p = (float)(N_) * (float)(N_) * b3[h];
    #pragma unroll 8
    for (int kk = 0; kk < 128; kk++) p += S[kk] * W3[kk * H_ + h];
    P[h] = p;
    __syncthreads();

    float o = c1[h];
    #pragma unroll 8
    for (int kk = 0; kk < 128; kk++) o += P[kk] * V1[kk * H_ + h];
    O[h] = fmaxf(o, 0.f);
    __syncthreads();

    if (h < OUT_) {
        float r = c2[h];
        #pragma unroll 8
        for (int kk = 0; kk < 128; kk++) r += O[kk] * V2[kk * OUT_ + h];
        out[b * OUT_ + h] = r;
    }
}

// =====================================================================
extern "C" void kernel_launch(void* const* d_in, const int* in_sizes, int n_in,
                              void* d_out, int out_size) {
    (void)in_sizes; (void)n_in; (void)out_size;
    const float* x  = (const float*)d_in[0];
    const float* W1 = (const float*)d_in[1];
    const float* b1 = (const float*)d_in[2];
    const float* W2 = (const float*)d_in[3];
    const float* b2 = (const float*)d_in[4];
    const float* W3 = (const float*)d_in[5];
    const float* b3 = (const float*)d_in[6];
    const float* V1 = (const float*)d_in[7];
    const float* c1 = (const float*)d_in[8];
    const float* V2 = (const float*)d_in[9];
    const float* c2 = (const float*)d_in[10];
    float* out = (float*)d_out;

    cudaFuncSetAttribute(main_kernel, cudaFuncAttributeMaxDynamicSharedMemorySize, SMEM_MAIN);

    convert_kernel<<<64, 256>>>(W1, W2);
    prep_kernel<<<(B_ * N_) / 2, 256>>>(x, b1);
    main_kernel<<<GRID_MAIN, 256, SMEM_MAIN>>>(b2);
    finish_kernel<<<B_, 128>>>(W3, b3, V1, c1, V2, c2, out);
}

// round 16
// speedup vs baseline: 1.9591x; 1.1541x over previous
#include <cuda_runtime.h>
#include <cuda_fp16.h>
#include <stdint.h>
#include <string.h>

// ---------------- problem constants ----------------
#define B_   2
#define N_   512
#define D_   64
#define H_   128
#define OUT_ 64
#define CPG  18                  // i-stride: CTAs per (b, j-block) group
#define GRID_MAIN (B_ * 4 * CPG) // 144 CTAs, ~1 per SM

// ---------------- device scratch (no allocs allowed) ----------------
__device__ __align__(16) __half g_xa [B_ * N_ * H_];   // x @ W1[:D]       (fp16)
__device__ __align__(16) __half g_xbp[B_ * N_ * H_];   // x @ W1[D:] + b1  (fp16)
__device__ __align__(16) uint2  g_w2f[8 * 16 * 32];    // W2 fragment-packed fp16
__device__ float g_part[GRID_MAIN * H_];               // per-CTA pooled partials
__device__ float g_dummy;                              // L2-warm sink (never read)

__device__ __forceinline__ __half2 as_h2(uint32_t u) { __half2 h; memcpy(&h, &u, 4); return h; }
__device__ __forceinline__ uint32_t as_u32(__half2 h) { uint32_t u; memcpy(&u, &h, 4); return u; }

// relu(a + b) on packed half2
__device__ __forceinline__ uint32_t relu_add2(uint32_t a, uint32_t b) {
    __half2 z = __float2half2_rn(0.f);
    return as_u32(__hmax2(__hadd2(as_h2(a), as_h2(b)), z));
}

// m16n8k16 row.col fp16 x fp16 -> fp16 accumulate (baseline PTX, sm_80+)
__device__ __forceinline__ void mma16816h(uint32_t* c, const uint32_t* a, uint32_t b0, uint32_t b1) {
    asm volatile(
        "mma.sync.aligned.m16n8k16.row.col.f16.f16.f16.f16 "
        "{%0,%1}, {%2,%3,%4,%5}, {%6,%7}, {%0,%1};"
        : "+r"(c[0]), "+r"(c[1])
        : "r"(a[0]), "r"(a[1]), "r"(a[2]), "r"(a[3]), "r"(b0), "r"(b1));
}

// ---------------- main-kernel SMEM layout (dynamic) ----------------
// W2F : 0      32768  (W2 fragments, [k8][nt16][lane32] x 8B; copied from g_w2f)
// XA  : 32768  34816  (128 rows x 272B padded fp16; staged once, read to regs)
// RED : 67584  2048   (8 warps x 64 cols fp32)
// B2  : 69632  512
#define SOFF_W2F 0
#define SOFF_XA  32768
#define SOFF_RED 67584
#define SOFF_B2  69632
#define XA_STRIDE 272
#define SMEM_MAIN (69632 + 512)

// =====================================================================
// Kernel 0: convert — W2 -> g_w2f (packed frags) + warm L2 with W3/V1/V2
// =====================================================================
__global__ void __launch_bounds__(256) convert_kernel(const float* __restrict__ W2,
                                                      const float* __restrict__ W3,
                                                      const float* __restrict__ V1,
                                                      const float* __restrict__ V2) {
    int i = blockIdx.x * 256 + threadIdx.x;   // 64*256 = 16384 threads
    if (i < 8 * 16 * 32) {
        int li = i & 31, nt = (i >> 5) & 15, k = i >> 9;
        int ltig = li & 3, lg = li >> 2;
        int col = nt * 8 + lg;
        int r0 = k * 16 + ltig * 2;
        uint32_t v0 = as_u32(__floats2half2_rn(W2[r0 * H_ + col],       W2[(r0 + 1) * H_ + col]));
        uint32_t v1 = as_u32(__floats2half2_rn(W2[(r0 + 8) * H_ + col], W2[(r0 + 9) * H_ + col]));
        g_w2f[i] = make_uint2(v0, v1);
    }
    // warm L2 for the finish-kernel weights (16K + 16K + 8K floats)
    float acc = 0.f;
    for (int q = i; q < H_ * H_; q += 16384) acc += W3[q] + V1[q];
    for (int q = i; q < H_ * OUT_; q += 16384) acc += V2[q];
    if (acc == -1.2345678e33f) g_dummy = acc;   // never true; defeats DCE
}

// =====================================================================
// Kernel 1: prep — xa = x @ W1[:64] (fp16), xbp = x @ W1[64:] + b1 (fp16)
// R10-proven version: 256 blocks x 256 threads, 4 rows/block, coalesced W1.
// =====================================================================
__global__ void __launch_bounds__(256) prep_kernel(const float* __restrict__ x,
                                                   const float* __restrict__ W1,
                                                   const float* __restrict__ b1) {
    __shared__ float xs[4][64];
    int tid  = threadIdx.x;
    int h    = tid & 127;
    int half = tid >> 7;                  // 0 -> xa, 1 -> xbp
    int row0 = blockIdx.x * 4;

    for (int q = tid; q < 4 * 64; q += 256)
        xs[q >> 6][q & 63] = x[row0 * 64 + q];

    float w[64];
    #pragma unroll
    for (int d = 0; d < 64; d++)
        w[d] = W1[(d + half * 64) * H_ + h];
    float bb = half ? b1[h] : 0.f;
    __syncthreads();

    #pragma unroll
    for (int rr = 0; rr < 4; rr++) {
        float p[8];
        #pragma unroll
        for (int j = 0; j < 8; j++) p[j] = 0.f;
        #pragma unroll
        for (int d8 = 0; d8 < 8; d8++)
            #pragma unroll
            for (int j = 0; j < 8; j++)
                p[j] += xs[rr][d8 * 8 + j] * w[d8 * 8 + j];
        float s = bb + (((p[0] + p[1]) + (p[2] + p[3])) + ((p[4] + p[5]) + (p[6] + p[7])));
        int row = row0 + rr;
        if (half) g_xbp[row * H_ + h] = __float2half(s);
        else      g_xa [row * H_ + h] = __float2half(s);
    }
}

// =====================================================================
// Kernel 2: main — 256 threads, 8 warps (R10 proven config, at HMMA floor).
// =====================================================================
__global__ void __launch_bounds__(256, 1) main_kernel(const float* __restrict__ b2) {
    extern __shared__ char smem[];

    int tid  = threadIdx.x;
    int wid  = tid >> 5;
    int lane = tid & 31;
    int tig  = lane & 3;      // k-pair / n-parity selector
    int g    = lane >> 2;     // row within 8
    int wn   = wid >> 2;      // warp col half: 0 -> cols 0..63, 1 -> 64..127
    int wm   = wid & 3;       // warp row quarter

    int grp = blockIdx.x / CPG;   // 0..7 : (b, jb)
    int cig = blockIdx.x % CPG;
    int b   = grp >> 2;
    int jb  = grp & 3;
    int ntiles = (N_ - cig + CPG - 1) / CPG;   // 28 or 29

    // --- copy pre-packed W2 fragments into smem ---
    {
        uint2* dst = (uint2*)(smem + SOFF_W2F);
        for (int idx = tid; idx < 8 * 16 * 32; idx += 256)
            dst[idx] = g_w2f[idx];
    }

    // --- stage xa tile (b, jb): 128 rows x 128 fp16, 272B padded stride ---
    {
        const float4* xag = (const float4*)(g_xa + (size_t)(b * N_ + jb * 128) * H_);
        for (int q = tid; q < 128 * 16; q += 256) {
            int r = q >> 4, f = q & 15;
            *(float4*)(smem + SOFF_XA + r * XA_STRIDE + f * 16) = xag[q];
        }
    }

    // --- b2 to smem (fp32) ---
    if (tid < 128) *(float*)(smem + SOFF_B2 + tid * 4) = b2[tid];

    __syncthreads();

    // --- hoist this thread's xa fragments into registers (invariant) ---
    uint32_t xar[8][8];   // [k][mt*4 + frag]
    {
        const char* xa_base = smem + SOFF_XA + (wm * 32 + g) * XA_STRIDE + tig * 4;
        #pragma unroll
        for (int k = 0; k < 8; k++) {
            #pragma unroll
            for (int mt = 0; mt < 2; mt++) {
                const char* p0 = xa_base + mt * 16 * XA_STRIDE + k * 32;
                const char* p1 = p0 + 8 * XA_STRIDE;
                xar[k][mt * 4 + 0] = *(const uint32_t*)(p0);
                xar[k][mt * 4 + 1] = *(const uint32_t*)(p1);
                xar[k][mt * 4 + 2] = *(const uint32_t*)(p0 + 16);
                xar[k][mt * 4 + 3] = *(const uint32_t*)(p1 + 16);
            }
        }
    }

    // --- per-thread b2 half2 biases for the epilogue ---
    uint32_t b2h[8];
    {
        const float* b2s = (const float*)(smem + SOFF_B2);
        #pragma unroll
        for (int n = 0; n < 8; n++) {
            int col = wn * 64 + n * 8 + tig * 2;
            b2h[n] = as_u32(__floats2half2_rn(b2s[col], b2s[col + 1]));
        }
    }

    const char* w2f_base = smem + SOFF_W2F + (size_t)(wn * 8) * 32 * 8 + lane * 8;
    const uint32_t* xbp_rows = (const uint32_t*)(g_xbp + (size_t)(b * N_) * H_);

    float pooled[8][2];
    #pragma unroll
    for (int n = 0; n < 8; n++) { pooled[n][0] = 0.f; pooled[n][1] = 0.f; }

    auto load_xb = [&](uint32_t* xb, int i) {
        const uint32_t* row = xbp_rows + (size_t)i * (H_ / 2);
        #pragma unroll
        for (int k = 0; k < 8; k++) {
            xb[k * 2]     = __ldg(row + k * 8 + tig);
            xb[k * 2 + 1] = __ldg(row + k * 8 + tig + 4);
        }
    };

    auto compute_tile = [&](const uint32_t* xb) {
        uint32_t acc[2][8][2];
        #pragma unroll
        for (int mt = 0; mt < 2; mt++)
            #pragma unroll
            for (int n = 0; n < 8; n++) { acc[mt][n][0] = 0u; acc[mt][n][1] = 0u; }

        #pragma unroll
        for (int k = 0; k < 8; k++) {
            uint32_t xb0 = xb[k * 2], xb1 = xb[k * 2 + 1];
            uint32_t a[2][4];
            #pragma unroll
            for (int mt = 0; mt < 2; mt++) {
                a[mt][0] = relu_add2(xar[k][mt * 4 + 0], xb0);
                a[mt][1] = relu_add2(xar[k][mt * 4 + 1], xb0);
                a[mt][2] = relu_add2(xar[k][mt * 4 + 2], xb1);
                a[mt][3] = relu_add2(xar[k][mt * 4 + 3], xb1);
            }
            const char* wp = w2f_base + (size_t)k * 16 * 32 * 8;
            #pragma unroll
            for (int n = 0; n < 8; n++) {
                uint2 bf = *(const uint2*)(wp + (size_t)n * 32 * 8);
                mma16816h(acc[0][n], a[0], bf.x, bf.y);
                mma16816h(acc[1][n], a[1], bf.x, bf.y);
            }
        }

        __half2 z = __float2half2_rn(0.f);
        #pragma unroll
        for (int n = 0; n < 8; n++) {
            #pragma unroll
            for (int mt = 0; mt < 2; mt++) {
                __half2 r0 = __hmax2(__hadd2(as_h2(acc[mt][n][0]), as_h2(b2h[n])), z);
                __half2 r1 = __hmax2(__hadd2(as_h2(acc[mt][n][1]), as_h2(b2h[n])), z);
                float2 f0 = __half22float2(r0);
                float2 f1 = __half22float2(r1);
                pooled[n][0] += f0.x + f1.x;
                pooled[n][1] += f0.y + f1.y;
            }
        }
    };

    // --- software-pipelined tile loop (xb prefetch in regs, no barriers) ---
    uint32_t xbA[16], xbB[16];
    load_xb(xbA, cig);
    for (int t = 0; t < ntiles; t += 2) {
        if (t + 1 < ntiles) load_xb(xbB, cig + (t + 1) * CPG);
        compute_tile(xbA);
        if (t + 1 < ntiles) {
            if (t + 2 < ntiles) load_xb(xbA, cig + (t + 2) * CPG);
            compute_tile(xbB);
        }
    }

    // --- deterministic reduction: shfl over rows, smem over warps ---
    float* red = (float*)(smem + SOFF_RED);
    #pragma unroll
    for (int n = 0; n < 8; n++) {
        #pragma unroll
        for (int p = 0; p < 2; p++) {
            float v = pooled[n][p];
            v += __shfl_xor_sync(0xFFFFFFFFu, v, 4);
            v += __shfl_xor_sync(0xFFFFFFFFu, v, 8);
            v += __shfl_xor_sync(0xFFFFFFFFu, v, 16);
            if (lane < 4) red[wid * 64 + n * 8 + lane * 2 + p] = v;
        }
    }
    __syncthreads();

    if (tid < 128) {
        int col = tid;
        int wbase = (col >> 6) * 4;
        int cl = col & 63;
        float s = red[(wbase + 0) * 64 + cl] + red[(wbase + 1) * 64 + cl]
                + red[(wbase + 2) * 64 + cl] + red[(wbase + 3) * 64 + cl];
        g_part[blockIdx.x * H_ + col] = s;
    }
}

// =====================================================================
// Kernel 3: finish — parallelized tiny MLP head.
// grid = 2 (one block per batch) x 512 threads; every GEMV stage k-split
// x4 with smem tree reduction; all weight loads coalesced across h.
// =====================================================================
__global__ void __launch_bounds__(512) finish_kernel(const float* __restrict__ W3,
                                                     const float* __restrict__ b3,
                                                     const float* __restrict__ V1,
                                                     const float* __restrict__ c1,
                                                     const float* __restrict__ V2,
                                                     const float* __restrict__ c2,
                                                     float* __restrict__ out) {
    int b   = blockIdx.x;
    int tid = threadIdx.x;
    int h   = tid & 127;
    int kq  = tid >> 7;            // 0..3

    __shared__ float T[4][128];
    __shared__ float S[128], P[128], O[128];
    __shared__ float R[8][64];

    // --- S[h] = sum over this batch's 72 CTA partials (k-split x4) ---
    {
        float s = 0.f;
        #pragma unroll 6
        for (int c = kq * 18; c < kq * 18 + 18; c++)
            s += g_part[(b * 4 * CPG + c) * H_ + h];
        T[kq][h] = s;
    }
    __syncthreads();
    if (kq == 0) S[h] = T[0][h] + T[1][h] + T[2][h] + T[3][h];
    __syncthreads();

    // --- P = S @ W3 + N^2*b3 ---
    {
        float p = 0.f;
        #pragma unroll 8
        for (int k = kq * 32; k < kq * 32 + 32; k++)
            p += S[k] * W3[k * H_ + h];
        T[kq][h] = p;
    }
    __syncthreads();
    if (kq == 0)
        P[h] = T[0][h] + T[1][h] + T[2][h] + T[3][h]
             + (float)N_ * (float)N_ * b3[h];
    __syncthreads();

    // --- O = relu(P @ V1 + c1) ---
    {
        float o = 0.f;
        #pragma unroll 8
        for (int k = kq * 32; k < kq * 32 + 32; k++)
            o += P[k] * V1[k * H_ + h];
        T[kq][h] = o;
    }
    __syncthreads();
    if (kq == 0)
        O[h] = fmaxf(T[0][h] + T[1][h] + T[2][h] + T[3][h] + c1[h], 0.f);
    __syncthreads();

    // --- out = O @ V2 + c2 (k-split x8 over 64 cols) ---
    {
        int c = tid & 63;
        int q = tid >> 6;          // 0..7, 16 k's each
        float r = 0.f;
        #pragma unroll 8
        for (int k = q * 16; k < q * 16 + 16; k++)
            r += O[k] * V2[k * OUT_ + c];
        R[q][c] = r;
    }
    __syncthreads();
    if (tid < 64) {
        float t = c2[tid];
        #pragma unroll
        for (int q = 0; q < 8; q++) t += R[q][tid];
        out[b * OUT_ + tid] = t;
    }
}

// =====================================================================
extern "C" void kernel_launch(void* const* d_in, const int* in_sizes, int n_in,
                              void* d_out, int out_size) {
    (void)in_sizes; (void)n_in; (void)out_size;
    const float* x  = (const float*)d_in[0];
    const float* W1 = (const float*)d_in[1];
    const float* b1 = (const float*)d_in[2];
    const float* W2 = (const float*)d_in[3];
    const float* b2 = (const float*)d_in[4];
    const float* W3 = (const float*)d_in[5];
    const float* b3 = (const float*)d_in[6];
    const float* V1 = (const float*)d_in[7];
    const float* c1 = (const float*)d_in[8];
    const float* V2 = (const float*)d_in[9];
    const float* c2 = (const float*)d_in[10];
    float* out = (float*)d_out;

    cudaFuncSetAttribute(main_kernel, cudaFuncAttributeMaxDynamicSharedMemorySize, SMEM_MAIN);

    convert_kernel<<<64, 256>>>(W2, W3, V1, V2);
    prep_kernel<<<(B_ * N_) / 4, 256>>>(x, W1, b1);
    main_kernel<<<GRID_MAIN, 256, SMEM_MAIN>>>(b2);
    finish_kernel<<<B_, 512>>>(W3, b3, V1, c1, V2, c2, out);
}

// round 17
// speedup vs baseline: 2.0208x; 1.0315x over previous
#include <cuda_runtime.h>
#include <cuda_fp16.h>
#include <stdint.h>
#include <string.h>

// ---------------- problem constants ----------------
#define B_   2
#define N_   512
#define D_   64
#define H_   128
#define OUT_ 64
#define CPG  18                  // i-stride: CTAs per (b, j-block) group
#define GRID_MAIN (B_ * 4 * CPG) // 144 CTAs, ~1 per SM

// ---------------- device scratch (no allocs allowed) ----------------
__device__ __align__(16) __half g_xa [B_ * N_ * H_];   // x @ W1[:D]       (fp16)
__device__ __align__(16) __half g_xbp[B_ * N_ * H_];   // x @ W1[D:] + b1  (fp16)
__device__ __align__(16) uint2  g_w2f[8 * 16 * 32];    // W2 fragment-packed fp16
__device__ float g_part[GRID_MAIN * H_];               // per-CTA pooled partials

__device__ __forceinline__ __half2 as_h2(uint32_t u) { __half2 h; memcpy(&h, &u, 4); return h; }
__device__ __forceinline__ uint32_t as_u32(__half2 h) { uint32_t u; memcpy(&u, &h, 4); return u; }

__device__ __forceinline__ uint32_t smem_u32(const void* p) {
    uint32_t a;
    asm("{ .reg .u64 t; cvta.to.shared.u64 t, %1; cvt.u32.u64 %0, t; }" : "=r"(a) : "l"(p));
    return a;
}

// 16B async copy global -> shared (baseline sm_80 PTX)
__device__ __forceinline__ void cp_async16(uint32_t saddr, const void* gptr) {
    asm volatile("cp.async.cg.shared.global [%0], [%1], 16;" :: "r"(saddr), "l"(gptr));
}
__device__ __forceinline__ void cp_async_commit() {
    asm volatile("cp.async.commit_group;" ::: "memory");
}
__device__ __forceinline__ void cp_async_wait_all() {
    asm volatile("cp.async.wait_group 0;" ::: "memory");
}

// relu(a + b) on packed half2
__device__ __forceinline__ uint32_t relu_add2(uint32_t a, uint32_t b) {
    __half2 z = __float2half2_rn(0.f);
    return as_u32(__hmax2(__hadd2(as_h2(a), as_h2(b)), z));
}

// m16n8k16 row.col fp16 x fp16 -> fp16 accumulate (baseline PTX, sm_80+)
__device__ __forceinline__ void mma16816h(uint32_t* c, const uint32_t* a, uint32_t b0, uint32_t b1) {
    asm volatile(
        "mma.sync.aligned.m16n8k16.row.col.f16.f16.f16.f16 "
        "{%0,%1}, {%2,%3,%4,%5}, {%6,%7}, {%0,%1};"
        : "+r"(c[0]), "+r"(c[1])
        : "r"(a[0]), "r"(a[1]), "r"(a[2]), "r"(a[3]), "r"(b0), "r"(b1));
}

// ---------------- main-kernel SMEM layout (dynamic) ----------------
#define SOFF_W2F 0
#define SOFF_XA  32768
#define SOFF_RED 67584
#define SOFF_B2  69632
#define XA_STRIDE 272
#define SMEM_MAIN (69632 + 512)

// ---------------- finish-kernel SMEM layout (dynamic) ----------------
#define FS_W3 0
#define FS_V1 65536
#define FS_V2 131072
#define SMEM_FIN (131072 + 32768)

// =====================================================================
// Kernel 1: prep+convert — blocks [0,256): xa/xbp rows; blocks [256,272):
// W2 fragment pack into g_w2f. One launch instead of two.
// =====================================================================
__global__ void __launch_bounds__(256) prep_kernel(const float* __restrict__ x,
                                                   const float* __restrict__ W1,
                                                   const float* __restrict__ b1,
                                                   const float* __restrict__ W2) {
    int tid = threadIdx.x;

    if (blockIdx.x >= 256) {
        // ---- W2 fragment pack (16 blocks x 256 thr = 4096 entries) ----
        int i = (blockIdx.x - 256) * 256 + tid;
        int li = i & 31, nt = (i >> 5) & 15, k = i >> 9;
        int ltig = li & 3, lg = li >> 2;
        int col = nt * 8 + lg;
        int r0 = k * 16 + ltig * 2;
        uint32_t v0 = as_u32(__floats2half2_rn(W2[r0 * H_ + col],       W2[(r0 + 1) * H_ + col]));
        uint32_t v1 = as_u32(__floats2half2_rn(W2[(r0 + 8) * H_ + col], W2[(r0 + 9) * H_ + col]));
        g_w2f[i] = make_uint2(v0, v1);
        return;
    }

    // ---- xa/xbp: 4 rows per block, coalesced W1 reads (R10-proven) ----
    __shared__ float xs[4][64];
    int h    = tid & 127;
    int half = tid >> 7;                  // 0 -> xa, 1 -> xbp
    int row0 = blockIdx.x * 4;

    for (int q = tid; q < 4 * 64; q += 256)
        xs[q >> 6][q & 63] = x[row0 * 64 + q];

    float w[64];
    #pragma unroll
    for (int d = 0; d < 64; d++)
        w[d] = W1[(d + half * 64) * H_ + h];
    float bb = half ? b1[h] : 0.f;
    __syncthreads();

    #pragma unroll
    for (int rr = 0; rr < 4; rr++) {
        float p[8];
        #pragma unroll
        for (int j = 0; j < 8; j++) p[j] = 0.f;
        #pragma unroll
        for (int d8 = 0; d8 < 8; d8++)
            #pragma unroll
            for (int j = 0; j < 8; j++)
                p[j] += xs[rr][d8 * 8 + j] * w[d8 * 8 + j];
        float s = bb + (((p[0] + p[1]) + (p[2] + p[3])) + ((p[4] + p[5]) + (p[6] + p[7])));
        int row = row0 + rr;
        if (half) g_xbp[row * H_ + h] = __float2half(s);
        else      g_xa [row * H_ + h] = __float2half(s);
    }
}

// =====================================================================
// Kernel 2: main — UNCHANGED from R16 (at fallback-HMMA pipe floor).
// =====================================================================
__global__ void __launch_bounds__(256, 1) main_kernel(const float* __restrict__ b2) {
    extern __shared__ char smem[];

    int tid  = threadIdx.x;
    int wid  = tid >> 5;
    int lane = tid & 31;
    int tig  = lane & 3;
    int g    = lane >> 2;
    int wn   = wid >> 2;
    int wm   = wid & 3;

    int grp = blockIdx.x / CPG;
    int cig = blockIdx.x % CPG;
    int b   = grp >> 2;
    int jb  = grp & 3;
    int ntiles = (N_ - cig + CPG - 1) / CPG;

    {
        uint2* dst = (uint2*)(smem + SOFF_W2F);
        for (int idx = tid; idx < 8 * 16 * 32; idx += 256)
            dst[idx] = g_w2f[idx];
    }
    {
        const float4* xag = (const float4*)(g_xa + (size_t)(b * N_ + jb * 128) * H_);
        for (int q = tid; q < 128 * 16; q += 256) {
            int r = q >> 4, f = q & 15;
            *(float4*)(smem + SOFF_XA + r * XA_STRIDE + f * 16) = xag[q];
        }
    }
    if (tid < 128) *(float*)(smem + SOFF_B2 + tid * 4) = b2[tid];

    __syncthreads();

    uint32_t xar[8][8];
    {
        const char* xa_base = smem + SOFF_XA + (wm * 32 + g) * XA_STRIDE + tig * 4;
        #pragma unroll
        for (int k = 0; k < 8; k++) {
            #pragma unroll
            for (int mt = 0; mt < 2; mt++) {
                const char* p0 = xa_base + mt * 16 * XA_STRIDE + k * 32;
                const char* p1 = p0 + 8 * XA_STRIDE;
                xar[k][mt * 4 + 0] = *(const uint32_t*)(p0);
                xar[k][mt * 4 + 1] = *(const uint32_t*)(p1);
                xar[k][mt * 4 + 2] = *(const uint32_t*)(p0 + 16);
                xar[k][mt * 4 + 3] = *(const uint32_t*)(p1 + 16);
            }
        }
    }

    uint32_t b2h[8];
    {
        const float* b2s = (const float*)(smem + SOFF_B2);
        #pragma unroll
        for (int n = 0; n < 8; n++) {
            int col = wn * 64 + n * 8 + tig * 2;
            b2h[n] = as_u32(__floats2half2_rn(b2s[col], b2s[col + 1]));
        }
    }

    const char* w2f_base = smem + SOFF_W2F + (size_t)(wn * 8) * 32 * 8 + lane * 8;
    const uint32_t* xbp_rows = (const uint32_t*)(g_xbp + (size_t)(b * N_) * H_);

    float pooled[8][2];
    #pragma unroll
    for (int n = 0; n < 8; n++) { pooled[n][0] = 0.f; pooled[n][1] = 0.f; }

    auto load_xb = [&](uint32_t* xb, int i) {
        const uint32_t* row = xbp_rows + (size_t)i * (H_ / 2);
        #pragma unroll
        for (int k = 0; k < 8; k++) {
            xb[k * 2]     = __ldg(row + k * 8 + tig);
            xb[k * 2 + 1] = __ldg(row + k * 8 + tig + 4);
        }
    };

    auto compute_tile = [&](const uint32_t* xb) {
        uint32_t acc[2][8][2];
        #pragma unroll
        for (int mt = 0; mt < 2; mt++)
            #pragma unroll
            for (int n = 0; n < 8; n++) { acc[mt][n][0] = 0u; acc[mt][n][1] = 0u; }

        #pragma unroll
        for (int k = 0; k < 8; k++) {
            uint32_t xb0 = xb[k * 2], xb1 = xb[k * 2 + 1];
            uint32_t a[2][4];
            #pragma unroll
            for (int mt = 0; mt < 2; mt++) {
                a[mt][0] = relu_add2(xar[k][mt * 4 + 0], xb0);
                a[mt][1] = relu_add2(xar[k][mt * 4 + 1], xb0);
                a[mt][2] = relu_add2(xar[k][mt * 4 + 2], xb1);
                a[mt][3] = relu_add2(xar[k][mt * 4 + 3], xb1);
            }
            const char* wp = w2f_base + (size_t)k * 16 * 32 * 8;
            #pragma unroll
            for (int n = 0; n < 8; n++) {
                uint2 bf = *(const uint2*)(wp + (size_t)n * 32 * 8);
                mma16816h(acc[0][n], a[0], bf.x, bf.y);
                mma16816h(acc[1][n], a[1], bf.x, bf.y);
            }
        }

        __half2 z = __float2half2_rn(0.f);
        #pragma unroll
        for (int n = 0; n < 8; n++) {
            #pragma unroll
            for (int mt = 0; mt < 2; mt++) {
                __half2 r0 = __hmax2(__hadd2(as_h2(acc[mt][n][0]), as_h2(b2h[n])), z);
                __half2 r1 = __hmax2(__hadd2(as_h2(acc[mt][n][1]), as_h2(b2h[n])), z);
                float2 f0 = __half22float2(r0);
                float2 f1 = __half22float2(r1);
                pooled[n][0] += f0.x + f1.x;
                pooled[n][1] += f0.y + f1.y;
            }
        }
    };

    uint32_t xbA[16], xbB[16];
    load_xb(xbA, cig);
    for (int t = 0; t < ntiles; t += 2) {
        if (t + 1 < ntiles) load_xb(xbB, cig + (t + 1) * CPG);
        compute_tile(xbA);
        if (t + 1 < ntiles) {
            if (t + 2 < ntiles) load_xb(xbA, cig + (t + 2) * CPG);
            compute_tile(xbB);
        }
    }

    float* red = (float*)(smem + SOFF_RED);
    #pragma unroll
    for (int n = 0; n < 8; n++) {
        #pragma unroll
        for (int p = 0; p < 2; p++) {
            float v = pooled[n][p];
            v += __shfl_xor_sync(0xFFFFFFFFu, v, 4);
            v += __shfl_xor_sync(0xFFFFFFFFu, v, 8);
            v += __shfl_xor_sync(0xFFFFFFFFu, v, 16);
            if (lane < 4) red[wid * 64 + n * 8 + lane * 2 + p] = v;
        }
    }
    __syncthreads();

    if (tid < 128) {
        int col = tid;
        int wbase = (col >> 6) * 4;
        int cl = col & 63;
        float s = red[(wbase + 0) * 64 + cl] + red[(wbase + 1) * 64 + cl]
                + red[(wbase + 2) * 64 + cl] + red[(wbase + 3) * 64 + cl];
        g_part[blockIdx.x * H_ + col] = s;
    }
}

// =====================================================================
// Kernel 3: finish — tiny MLP head with cp.async weight prefetch.
// Weights (W3/V1/V2, 160 KB) stream into smem overlapped with the g_part
// reduction; every GEMV stage reads smem (29 cyc) instead of L2 (234+).
// =====================================================================
__global__ void __launch_bounds__(512) finish_kernel(const float* __restrict__ W3,
                                                     const float* __restrict__ b3,
                                                     const float* __restrict__ V1,
                                                     const float* __restrict__ c1,
                                                     const float* __restrict__ V2,
                                                     const float* __restrict__ c2,
                                                     float* __restrict__ out) {
    extern __shared__ char fsm[];
    __shared__ float T[4][128];
    __shared__ float S[128], P[128], O[128];
    __shared__ float R[8][64];

    int b   = blockIdx.x;
    int tid = threadIdx.x;
    int h   = tid & 127;
    int kq  = tid >> 7;            // 0..3

    // --- prefetch all weights to smem (overlaps with reduction below) ---
    {
        uint32_t sb = smem_u32(fsm);
        for (int q = tid; q < 4096; q += 512) cp_async16(sb + FS_W3 + q * 16, W3 + q * 4);
        for (int q = tid; q < 4096; q += 512) cp_async16(sb + FS_V1 + q * 16, V1 + q * 4);
        for (int q = tid; q < 2048; q += 512) cp_async16(sb + FS_V2 + q * 16, V2 + q * 4);
        cp_async_commit();
    }

    // --- S[h] = sum over this batch's 72 CTA partials (k-split x4) ---
    {
        float s = 0.f;
        #pragma unroll 6
        for (int c = kq * 18; c < kq * 18 + 18; c++)
            s += g_part[(b * 4 * CPG + c) * H_ + h];
        T[kq][h] = s;
    }
    __syncthreads();
    if (kq == 0) S[h] = T[0][h] + T[1][h] + T[2][h] + T[3][h];

    cp_async_wait_all();
    __syncthreads();

    const float* W3s = (const float*)(fsm + FS_W3);
    const float* V1s = (const float*)(fsm + FS_V1);
    const float* V2s = (const float*)(fsm + FS_V2);

    // --- P = S @ W3 + N^2*b3 ---
    {
        float p = 0.f;
        #pragma unroll 8
        for (int k = kq * 32; k < kq * 32 + 32; k++)
            p += S[k] * W3s[k * H_ + h];
        T[kq][h] = p;
    }
    __syncthreads();
    if (kq == 0)
        P[h] = T[0][h] + T[1][h] + T[2][h] + T[3][h]
             + (float)N_ * (float)N_ * b3[h];
    __syncthreads();

    // --- O = relu(P @ V1 + c1) ---
    {
        float o = 0.f;
        #pragma unroll 8
        for (int k = kq * 32; k < kq * 32 + 32; k++)
            o += P[k] * V1s[k * H_ + h];
        T[kq][h] = o;
    }
    __syncthreads();
    if (kq == 0)
        O[h] = fmaxf(T[0][h] + T[1][h] + T[2][h] + T[3][h] + c1[h], 0.f);
    __syncthreads();

    // --- out = O @ V2 + c2 (k-split x8 over 64 cols) ---
    {
        int c = tid & 63;
        int q = tid >> 6;          // 0..7, 16 k's each
        float r = 0.f;
        #pragma unroll 8
        for (int k = q * 16; k < q * 16 + 16; k++)
            r += O[k] * V2s[k * OUT_ + c];
        R[q][c] = r;
    }
    __syncthreads();
    if (tid < 64) {
        float t = c2[tid];
        #pragma unroll
        for (int q = 0; q < 8; q++) t += R[q][tid];
        out[b * OUT_ + tid] = t;
    }
}

// =====================================================================
extern "C" void kernel_launch(void* const* d_in, const int* in_sizes, int n_in,
                              void* d_out, int out_size) {
    (void)in_sizes; (void)n_in; (void)out_size;
    const float* x  = (const float*)d_in[0];
    const float* W1 = (const float*)d_in[1];
    const float* b1 = (const float*)d_in[2];
    const float* W2 = (const float*)d_in[3];
    const float* b2 = (const float*)d_in[4];
    const float* W3 = (const float*)d_in[5];
    const float* b3 = (const float*)d_in[6];
    const float* V1 = (const float*)d_in[7];
    const float* c1 = (const float*)d_in[8];
    const float* V2 = (const float*)d_in[9];
    const float* c2 = (const float*)d_in[10];
    float* out = (float*)d_out;

    cudaFuncSetAttribute(main_kernel,   cudaFuncAttributeMaxDynamicSharedMemorySize, SMEM_MAIN);
    cudaFuncSetAttribute(finish_kernel, cudaFuncAttributeMaxDynamicSharedMemorySize, SMEM_FIN);

    prep_kernel<<<256 + 16, 256>>>(x, W1, b1, W2);
    main_kernel<<<GRID_MAIN, 256, SMEM_MAIN>>>(b2);
    finish_kernel<<<B_, 512, SMEM_FIN>>>(W3, b3, V1, c1, V2, c2, out);
}